// round 8
// baseline (speedup 1.0000x reference)
#include <cuda_runtime.h>
#include <cstdint>

#define BB 2
#define SS 2048
#define HH 16
#define DD 64
#define EE 1024
#define MM (BB*SS)        /* 4096 */
#define N3 (3*EE)         /* 3072 */
#define OUTN (MM*EE)      /* 4194304 */

// dynamic smem layout for GEMM (32-bit words): [A0][A1][B0][B1]
#define ASZ (128*36)      /* 4608 words per A buffer */
#define BSZ (32*132)      /* 4224 words per B buffer */
#define GEMM_SMEM_BYTES ((2*ASZ + 2*BSZ) * 4)   /* 70656 B */

// Scratch (allocation-free rule: __device__ globals)
__device__ float g_q[BB*HH*SS*DD];     // q in [B,H,S,D]
__device__ float g_attn[MM*EE];        // attention output, [B,S,E] row-major
__device__ float g_kscr[BB*HH*SS*DD];  // fallback if harness only wants `out`
__device__ float g_vscr[BB*HH*SS*DD];

__device__ __forceinline__ uint32_t f2tf32(float f) {
    uint32_t r;
    asm("cvt.rna.tf32.f32 %0, %1;" : "=r"(r) : "f"(f));
    return r;
}

__device__ __forceinline__ void mma_tf32(float c[4], const uint32_t a[4], const uint32_t b[2]) {
    asm volatile(
        "mma.sync.aligned.m16n8k8.row.col.f32.tf32.tf32.f32 "
        "{%0,%1,%2,%3}, {%4,%5,%6,%7}, {%8,%9}, {%0,%1,%2,%3};"
        : "+f"(c[0]), "+f"(c[1]), "+f"(c[2]), "+f"(c[3])
        : "r"(a[0]), "r"(a[1]), "r"(a[2]), "r"(a[3]), "r"(b[0]), "r"(b[1]));
}

// ---------------------------------------------------------------------------
// tf32 tensor-core GEMM: C[M,NDIM] = A[M,1024] * B[1024,NDIM] + bias
// Block tile 128x128, K-step 32, 256 threads (8 warps, 4x2 warp grid),
// warp tile 32x64. Double-buffered smem, ONE syncthreads per K-tile.
// EPI=1: QKV scatter epilogue.
// ---------------------------------------------------------------------------
template<int NDIM, int EPI>
__global__ __launch_bounds__(256, 1) void mma_gemm_kernel(
    const float* __restrict__ A, const float* __restrict__ Bw,
    const float* __restrict__ bias,
    float* __restrict__ out0, float* __restrict__ out1, float* __restrict__ out2)
{
    extern __shared__ uint32_t sm[];   // [A0][A1][B0][B1]

    const int tid  = threadIdx.x;
    const int lane = tid & 31;
    const int warp = tid >> 5;
    const int wm   = warp & 3;
    const int wn   = warp >> 2;
    const int m0   = blockIdx.y * 128;
    const int n0   = blockIdx.x * 128;
    const int lq   = lane >> 2;
    const int lr   = lane & 3;

    float acc[2][8][4];
#pragma unroll
    for (int i = 0; i < 2; i++)
#pragma unroll
        for (int j = 0; j < 8; j++)
#pragma unroll
            for (int t = 0; t < 4; t++) acc[i][j][t] = 0.f;

    float4 pa[4], pb[4];

    auto ldg = [&](int k0) {
#pragma unroll
        for (int i = 0; i < 4; i++) {
            const int idx = i * 256 + tid;
            pa[i] = *(const float4*)&A[(size_t)(m0 + (idx >> 3)) * EE + k0 + ((idx & 7) << 2)];
            pb[i] = *(const float4*)&Bw[(size_t)(k0 + (idx >> 5)) * NDIM + n0 + ((idx & 31) << 2)];
        }
    };
    auto sts = [&](int buf) {
        uint32_t* Asb = sm + buf * ASZ;
        uint32_t* Bsb = sm + 2 * ASZ + buf * BSZ;
#pragma unroll
        for (int i = 0; i < 4; i++) {
            const int idx = i * 256 + tid;
            *(uint4*)&Asb[(idx >> 3) * 36 + ((idx & 7) << 2)] =
                make_uint4(f2tf32(pa[i].x), f2tf32(pa[i].y), f2tf32(pa[i].z), f2tf32(pa[i].w));
            *(uint4*)&Bsb[(idx >> 5) * 132 + ((idx & 31) << 2)] =
                make_uint4(f2tf32(pb[i].x), f2tf32(pb[i].y), f2tf32(pb[i].z), f2tf32(pb[i].w));
        }
    };

    // prologue: tile0 -> buf0, tile1 staged in regs
    ldg(0);
    sts(0);
    ldg(32);
    __syncthreads();

    for (int t = 0; t < 32; t++) {
        const int cur = t & 1;
        // stage next tile into the other buffer, fetch tile t+2
        if (t + 1 < 32) {
            sts(cur ^ 1);
            if (t + 2 < 32) ldg((t + 2) * 32);
        }
        const uint32_t* Asb = sm + cur * ASZ;
        const uint32_t* Bsb = sm + 2 * ASZ + cur * BSZ;

#pragma unroll
        for (int kk = 0; kk < 32; kk += 8) {
            uint32_t af[2][4], bf[8][2];
#pragma unroll
            for (int mt = 0; mt < 2; mt++) {
                const int row = wm * 32 + mt * 16 + lq;
                af[mt][0] = Asb[row * 36 + kk + lr];
                af[mt][1] = Asb[(row + 8) * 36 + kk + lr];
                af[mt][2] = Asb[row * 36 + kk + lr + 4];
                af[mt][3] = Asb[(row + 8) * 36 + kk + lr + 4];
            }
#pragma unroll
            for (int nt = 0; nt < 8; nt++) {
                const int col = wn * 64 + nt * 8 + lq;
                bf[nt][0] = Bsb[(kk + lr) * 132 + col];
                bf[nt][1] = Bsb[(kk + lr + 4) * 132 + col];
            }
#pragma unroll
            for (int mt = 0; mt < 2; mt++)
#pragma unroll
                for (int nt = 0; nt < 8; nt++)
                    mma_tf32(acc[mt][nt], af[mt], bf[nt]);
        }
        __syncthreads();
    }

#pragma unroll
    for (int mt = 0; mt < 2; mt++) {
        const int mA = m0 + wm * 32 + mt * 16 + lq;
        const int mB = mA + 8;
#pragma unroll
        for (int nt = 0; nt < 8; nt++) {
            const int n  = n0 + wn * 64 + nt * 8 + 2 * lr;
            const float bs0 = bias[n], bs1 = bias[n + 1];
            float2 vA = make_float2(acc[mt][nt][0] + bs0, acc[mt][nt][1] + bs1);
            float2 vB = make_float2(acc[mt][nt][2] + bs0, acc[mt][nt][3] + bs1);
            if (EPI == 0) {
                *(float2*)&out0[(size_t)mA * NDIM + n] = vA;
                *(float2*)&out0[(size_t)mB * NDIM + n] = vB;
            } else {
                const int seg = n >> 10;
                const int c   = n & 1023;
                const int h   = c >> 6;
                const int d   = c & 63;
                float* dst = (seg == 0) ? out0 : ((seg == 1) ? out1 : out2);
                const int bA = mA >> 11, sA = mA & 2047;
                const int bB = mB >> 11, sB = mB & 2047;
                *(float2*)&dst[(((size_t)(bA * HH) + h) * SS + sA) * DD + d] = vA;
                *(float2*)&dst[(((size_t)(bB * HH) + h) * SS + sB) * DD + d] = vB;
            }
        }
    }
}

// ---------------------------------------------------------------------------
// tf32 tensor-core flash attention, causal. (unchanged from Round-6 passing)
// Block = 64 queries (4 warps x 16 rows), K-tile = 64 keys, D = 64.
// ---------------------------------------------------------------------------
__global__ __launch_bounds__(128) void attn_mma_kernel(
    const float* __restrict__ Q, const float* __restrict__ K,
    const float* __restrict__ V, float* __restrict__ O)
{
    __shared__ uint32_t Ks[64][68];
    __shared__ uint32_t Vs[64][72];

    const int tid  = threadIdx.x;
    const int lane = tid & 31;
    const int warp = tid >> 5;
    const int lq   = lane >> 2;
    const int lr   = lane & 3;
    const int qt = blockIdx.x, h = blockIdx.y, b = blockIdx.z;

    const size_t bho = (size_t)(b * HH + h) * SS * DD;
    const float* Qb = Q + bho;
    const float* Kb = K + bho;
    const float* Vb = V + bho;

    const int q0  = qt * 64 + warp * 16;
    const int qg0 = q0 + lq;        // row A (acc c0,c1)
    const int qg1 = q0 + lq + 8;    // row B (acc c2,c3)

    // Q fragments, pre-scaled by 1/sqrt(64)=0.125, tf32
    uint32_t qa[8][4];
#pragma unroll
    for (int kk8 = 0; kk8 < 8; kk8++) {
        const int d0 = kk8 * 8;
        qa[kk8][0] = f2tf32(Qb[(size_t)qg0 * DD + d0 + lr]     * 0.125f);
        qa[kk8][1] = f2tf32(Qb[(size_t)qg1 * DD + d0 + lr]     * 0.125f);
        qa[kk8][2] = f2tf32(Qb[(size_t)qg0 * DD + d0 + lr + 4] * 0.125f);
        qa[kk8][3] = f2tf32(Qb[(size_t)qg1 * DD + d0 + lr + 4] * 0.125f);
    }

    float oacc[8][4];
#pragma unroll
    for (int nt = 0; nt < 8; nt++)
#pragma unroll
        for (int t = 0; t < 4; t++) oacc[nt][t] = 0.f;
    float m0 = -1e30f, m1 = -1e30f, l0 = 0.f, l1 = 0.f;

    for (int kt = 0; kt <= qt; kt++) {
        __syncthreads();   // prior tile's PV reads of Ks(P)/Vs are done
#pragma unroll
        for (int i = 0; i < 8; i++) {
            const int idx = i * 128 + tid;
            const int row = idx >> 4;
            const int c4  = (idx & 15) << 2;
            float4 kv = *(const float4*)&Kb[(size_t)(kt * 64 + row) * DD + c4];
            float4 vv = *(const float4*)&Vb[(size_t)(kt * 64 + row) * DD + c4];
            Ks[row][c4+0] = f2tf32(kv.x); Ks[row][c4+1] = f2tf32(kv.y);
            Ks[row][c4+2] = f2tf32(kv.z); Ks[row][c4+3] = f2tf32(kv.w);
            Vs[row][c4+0] = f2tf32(vv.x); Vs[row][c4+1] = f2tf32(vv.y);
            Vs[row][c4+2] = f2tf32(vv.z); Vs[row][c4+3] = f2tf32(vv.w);
        }
        __syncthreads();

        // --- scores: S = (Q*scale) . K^T ---
        float sacc[8][4];
#pragma unroll
        for (int nt = 0; nt < 8; nt++)
#pragma unroll
            for (int t = 0; t < 4; t++) sacc[nt][t] = 0.f;
#pragma unroll
        for (int kk8 = 0; kk8 < 8; kk8++) {
#pragma unroll
            for (int nt = 0; nt < 8; nt++) {
                uint32_t bf[2];
                bf[0] = Ks[nt * 8 + lq][kk8 * 8 + lr];
                bf[1] = Ks[nt * 8 + lq][kk8 * 8 + lr + 4];
                mma_tf32(sacc[nt], qa[kk8], bf);
            }
        }

        // --- causal mask + row max ---
        float rmax0 = m0, rmax1 = m1;
#pragma unroll
        for (int nt = 0; nt < 8; nt++) {
            const int gk = kt * 64 + nt * 8 + 2 * lr;
            if (gk     > qg0) sacc[nt][0] = -1e30f;
            if (gk + 1 > qg0) sacc[nt][1] = -1e30f;
            if (gk     > qg1) sacc[nt][2] = -1e30f;
            if (gk + 1 > qg1) sacc[nt][3] = -1e30f;
            rmax0 = fmaxf(rmax0, fmaxf(sacc[nt][0], sacc[nt][1]));
            rmax1 = fmaxf(rmax1, fmaxf(sacc[nt][2], sacc[nt][3]));
        }
        rmax0 = fmaxf(rmax0, __shfl_xor_sync(0xffffffffu, rmax0, 1));
        rmax0 = fmaxf(rmax0, __shfl_xor_sync(0xffffffffu, rmax0, 2));
        rmax1 = fmaxf(rmax1, __shfl_xor_sync(0xffffffffu, rmax1, 1));
        rmax1 = fmaxf(rmax1, __shfl_xor_sync(0xffffffffu, rmax1, 2));

        const float a0 = __expf(m0 - rmax0);
        const float a1 = __expf(m1 - rmax1);
        m0 = rmax0; m1 = rmax1;

        float ls0 = 0.f, ls1 = 0.f;
#pragma unroll
        for (int nt = 0; nt < 8; nt++) {
            sacc[nt][0] = __expf(sacc[nt][0] - m0);
            sacc[nt][1] = __expf(sacc[nt][1] - m0);
            sacc[nt][2] = __expf(sacc[nt][2] - m1);
            sacc[nt][3] = __expf(sacc[nt][3] - m1);
            ls0 += sacc[nt][0] + sacc[nt][1];
            ls1 += sacc[nt][2] + sacc[nt][3];
        }
        ls0 += __shfl_xor_sync(0xffffffffu, ls0, 1);
        ls0 += __shfl_xor_sync(0xffffffffu, ls0, 2);
        ls1 += __shfl_xor_sync(0xffffffffu, ls1, 1);
        ls1 += __shfl_xor_sync(0xffffffffu, ls1, 2);
        l0 = l0 * a0 + ls0;
        l1 = l1 * a1 + ls1;

#pragma unroll
        for (int nt = 0; nt < 8; nt++) {
            oacc[nt][0] *= a0; oacc[nt][1] *= a0;
            oacc[nt][2] *= a1; oacc[nt][3] *= a1;
        }

        __syncthreads();   // all warps done reading Ks -> safe to overwrite with P

        uint32_t* Ps = &Ks[warp * 16][0];
#pragma unroll
        for (int nt = 0; nt < 8; nt++) {
            uint2 p0 = make_uint2(f2tf32(sacc[nt][0]), f2tf32(sacc[nt][1]));
            uint2 p1 = make_uint2(f2tf32(sacc[nt][2]), f2tf32(sacc[nt][3]));
            *(uint2*)&Ps[lq * 68 + nt * 8 + 2 * lr]       = p0;
            *(uint2*)&Ps[(lq + 8) * 68 + nt * 8 + 2 * lr] = p1;
        }
        __syncwarp();

        // --- O += P . V ---
#pragma unroll
        for (int kk8 = 0; kk8 < 8; kk8++) {
            uint32_t af[4];
            af[0] = Ps[lq * 68 + kk8 * 8 + lr];
            af[1] = Ps[(lq + 8) * 68 + kk8 * 8 + lr];
            af[2] = Ps[lq * 68 + kk8 * 8 + lr + 4];
            af[3] = Ps[(lq + 8) * 68 + kk8 * 8 + lr + 4];
#pragma unroll
            for (int nt = 0; nt < 8; nt++) {
                uint32_t bf[2];
                bf[0] = Vs[kk8 * 8 + lr][nt * 8 + lq];
                bf[1] = Vs[kk8 * 8 + lr + 4][nt * 8 + lq];
                mma_tf32(oacc[nt], af, bf);
            }
        }
    }

    // epilogue: normalize, write [B,S,E] row-major for the proj GEMM
    const float inv0 = 1.f / l0;
    const float inv1 = 1.f / l1;
    const size_t r0 = (size_t)(b * SS + qg0) * EE + h * 64;
    const size_t r1 = (size_t)(b * SS + qg1) * EE + h * 64;
#pragma unroll
    for (int nt = 0; nt < 8; nt++) {
        float2 v0 = make_float2(oacc[nt][0] * inv0, oacc[nt][1] * inv0);
        float2 v1 = make_float2(oacc[nt][2] * inv1, oacc[nt][3] * inv1);
        *(float2*)&O[r0 + nt * 8 + 2 * lr] = v0;
        *(float2*)&O[r1 + nt * 8 + 2 * lr] = v1;
    }
}

// ---------------------------------------------------------------------------
extern "C" void kernel_launch(void* const* d_in, const int* in_sizes, int n_in,
                              void* d_out, int out_size)
{
    const float* x      = (const float*)d_in[0];
    const float* qkv_w  = (const float*)d_in[1];
    const float* qkv_b  = (const float*)d_in[2];
    const float* proj_w = (const float*)d_in[3];
    const float* proj_b = (const float*)d_in[4];
    float* out = (float*)d_out;

    float *qbuf, *attnbuf, *kscr, *vscr;
    cudaGetSymbolAddress((void**)&qbuf,    g_q);
    cudaGetSymbolAddress((void**)&attnbuf, g_attn);
    cudaGetSymbolAddress((void**)&kscr,    g_kscr);
    cudaGetSymbolAddress((void**)&vscr,    g_vscr);

    const bool kv_in_out = (out_size >= 3*OUTN);
    float* kdst = kv_in_out ? (out + OUTN)   : kscr;
    float* vdst = kv_in_out ? (out + 2*OUTN) : vscr;

    // dynamic smem (70.7 KB) needs the opt-in attribute; idempotent host call
    cudaFuncSetAttribute(mma_gemm_kernel<N3, 1>,
                         cudaFuncAttributeMaxDynamicSharedMemorySize, GEMM_SMEM_BYTES);
    cudaFuncSetAttribute(mma_gemm_kernel<EE, 0>,
                         cudaFuncAttributeMaxDynamicSharedMemorySize, GEMM_SMEM_BYTES);

    mma_gemm_kernel<N3, 1><<<dim3(N3/128, MM/128), 256, GEMM_SMEM_BYTES>>>(
        x, qkv_w, qkv_b, qbuf, kdst, vdst);
    attn_mma_kernel<<<dim3(SS/64, HH, BB), 128>>>(qbuf, kdst, vdst, attnbuf);
    mma_gemm_kernel<EE, 0><<<dim3(EE/128, MM/128), 256, GEMM_SMEM_BYTES>>>(
        attnbuf, proj_w, proj_b, out, nullptr, nullptr);
}

// round 14
// speedup vs baseline: 1.1585x; 1.1585x over previous
#include <cuda_runtime.h>
#include <cstdint>

#define BB 2
#define SS 2048
#define HH 16
#define DD 64
#define EE 1024
#define MM (BB*SS)        /* 4096 */
#define N3 (3*EE)         /* 3072 */
#define OUTN (MM*EE)      /* 4194304 */

// fragment-major permuted smem, 32-bit words: [A0][A1][B0][B1]
// A chunk index g = (m/16)*4 + (k/8) in [0,32); word = (g*33+lane)*4 + s
// B chunk index h = (k/8)*8 + (n/16) in [0,32); word = (h*33+lane)*4 + w
#define ASZ 4224
#define BSZ 4224
#define GEMM_SMEM_BYTES ((2*ASZ + 2*BSZ) * 4)   /* 67584 B */

// Scratch (allocation-free rule: __device__ globals)
__device__ float g_q[BB*HH*SS*DD];     // q in [B,H,S,D]
__device__ float g_attn[MM*EE];        // attention output, [B,S,E] row-major
__device__ float g_kscr[BB*HH*SS*DD];  // fallback if harness only wants `out`
__device__ float g_vscr[BB*HH*SS*DD];

__device__ __forceinline__ uint32_t f2tf32(float f) {
    uint32_t r;
    asm("cvt.rna.tf32.f32 %0, %1;" : "=r"(r) : "f"(f));
    return r;
}

__device__ __forceinline__ void mma_tf32(float c[4], const uint32_t a[4], const uint32_t b[2]) {
    asm volatile(
        "mma.sync.aligned.m16n8k8.row.col.f32.tf32.tf32.f32 "
        "{%0,%1,%2,%3}, {%4,%5,%6,%7}, {%8,%9}, {%0,%1,%2,%3};"
        : "+f"(c[0]), "+f"(c[1]), "+f"(c[2]), "+f"(c[3])
        : "r"(a[0]), "r"(a[1]), "r"(a[2]), "r"(a[3]), "r"(b[0]), "r"(b[1]));
}

// ---------------------------------------------------------------------------
// tf32 tensor-core GEMM: C[M,NDIM] = A[M,1024] * B[1024,NDIM] + bias
// Block tile 128x128, K-step 32, 256 threads (8 warps, 4x2 warp grid),
// warp tile 32x64. Double-buffered fragment-major smem: every fragment
// load is one LDS.128, conflict-free. EPI=1: QKV scatter epilogue.
// ---------------------------------------------------------------------------
template<int NDIM, int EPI>
__global__ __launch_bounds__(256, 1) void mma_gemm_kernel(
    const float* __restrict__ A, const float* __restrict__ Bw,
    const float* __restrict__ bias,
    float* __restrict__ out0, float* __restrict__ out1, float* __restrict__ out2)
{
    extern __shared__ uint32_t sm[];   // [A0][A1][B0][B1]

    const int tid  = threadIdx.x;
    const int lane = tid & 31;
    const int warp = tid >> 5;
    const int wm   = warp & 3;
    const int wn   = warp >> 2;
    const int m0   = blockIdx.y * 128;
    const int n0   = blockIdx.x * 128;
    const int lq   = lane >> 2;
    const int lr   = lane & 3;

    float acc[2][8][4];
#pragma unroll
    for (int i = 0; i < 2; i++)
#pragma unroll
        for (int j = 0; j < 8; j++)
#pragma unroll
            for (int t = 0; t < 4; t++) acc[i][j][t] = 0.f;

    float4 pa[4], pb[4];

    auto ldg = [&](int k0) {
#pragma unroll
        for (int i = 0; i < 4; i++) {
            const int idx = i * 256 + tid;
            pa[i] = *(const float4*)&A[(size_t)(m0 + (idx >> 3)) * EE + k0 + ((idx & 7) << 2)];
            pb[i] = *(const float4*)&Bw[(size_t)(k0 + (idx >> 5)) * NDIM + n0 + ((idx & 31) << 2)];
        }
    };
    // fragment-major scatter store
    auto sts = [&](int buf) {
        uint32_t* Ap = sm + buf * ASZ;
        uint32_t* Bp = sm + 2 * ASZ + buf * BSZ;
#pragma unroll
        for (int i = 0; i < 4; i++) {
            const int idx = i * 256 + tid;
            // A element (am, ak4..ak4+3)
            const int am  = idx >> 3, ak4 = (idx & 7) << 2;
            const int gA  = (am >> 4) * 4 + (ak4 >> 3);
            const int sA  = ((am >> 3) & 1) + ((ak4 >> 2) & 1) * 2;
            const int lbA = (am & 7) * 4;
            const float* av = (const float*)&pa[i];
#pragma unroll
            for (int j = 0; j < 4; j++)
                Ap[(gA * 33 + lbA + j) * 4 + sA] = f2tf32(av[j]);
            // B element (bk, bn4..bn4+3)
            const int bk  = idx >> 5, bn4 = (idx & 31) << 2;
            const int kk8 = bk >> 3;
            const int slot = (bk >> 2) & 1;
            const int nt  = bn4 >> 3;           // 0..15 (bn4%8 in {0,4})
            const int hB  = kk8 * 8 + (nt >> 1);
            const int wB  = (nt & 1) * 2 + slot;
            const float* bv = (const float*)&pb[i];
#pragma unroll
            for (int j = 0; j < 4; j++) {
                const int laneB = ((bn4 & 4) + j) * 4 + (bk & 3);
                Bp[(hB * 33 + laneB) * 4 + wB] = f2tf32(bv[j]);
            }
        }
    };

    // prologue: tile0 -> buf0, tile1 staged in regs
    ldg(0);
    sts(0);
    ldg(32);
    __syncthreads();

    for (int t = 0; t < 32; t++) {
        const int cur = t & 1;
        if (t + 1 < 32) {
            sts(cur ^ 1);
            if (t + 2 < 32) ldg((t + 2) * 32);
        }
        const uint32_t* Asb = sm + cur * ASZ;
        const uint32_t* Bsb = sm + 2 * ASZ + cur * BSZ;

#pragma unroll
        for (int kk8 = 0; kk8 < 4; kk8++) {
            uint32_t af[2][4];
#pragma unroll
            for (int mt = 0; mt < 2; mt++) {
                const int g = (wm * 2 + mt) * 4 + kk8;
                *(uint4*)&af[mt][0] = *(const uint4*)&Asb[(g * 33 + lane) * 4];
            }
            uint32_t bq[4][4];   // [q] = {nt0 s0, nt0 s1, nt1 s0, nt1 s1}
#pragma unroll
            for (int q = 0; q < 4; q++) {
                const int h = kk8 * 8 + wn * 4 + q;
                *(uint4*)&bq[q][0] = *(const uint4*)&Bsb[(h * 33 + lane) * 4];
            }
#pragma unroll
            for (int mt = 0; mt < 2; mt++)
#pragma unroll
                for (int nt = 0; nt < 8; nt++) {
                    uint32_t bf[2] = { bq[nt >> 1][(nt & 1) * 2],
                                       bq[nt >> 1][(nt & 1) * 2 + 1] };
                    mma_tf32(acc[mt][nt], af[mt], bf);
                }
        }
        __syncthreads();
    }

#pragma unroll
    for (int mt = 0; mt < 2; mt++) {
        const int mA = m0 + wm * 32 + mt * 16 + lq;
        const int mB = mA + 8;
#pragma unroll
        for (int nt = 0; nt < 8; nt++) {
            const int n  = n0 + wn * 64 + nt * 8 + 2 * lr;
            const float bs0 = bias[n], bs1 = bias[n + 1];
            float2 vA = make_float2(acc[mt][nt][0] + bs0, acc[mt][nt][1] + bs1);
            float2 vB = make_float2(acc[mt][nt][2] + bs0, acc[mt][nt][3] + bs1);
            if (EPI == 0) {
                *(float2*)&out0[(size_t)mA * NDIM + n] = vA;
                *(float2*)&out0[(size_t)mB * NDIM + n] = vB;
            } else {
                const int seg = n >> 10;
                const int c   = n & 1023;
                const int h   = c >> 6;
                const int d   = c & 63;
                float* dst = (seg == 0) ? out0 : ((seg == 1) ? out1 : out2);
                const int bA = mA >> 11, sA = mA & 2047;
                const int bB = mB >> 11, sB = mB & 2047;
                *(float2*)&dst[(((size_t)(bA * HH) + h) * SS + sA) * DD + d] = vA;
                *(float2*)&dst[(((size_t)(bB * HH) + h) * SS + sB) * DD + d] = vB;
            }
        }
    }
}

// ---------------------------------------------------------------------------
// tf32 tensor-core flash attention, causal. (unchanged from Round-6 passing)
// Block = 64 queries (4 warps x 16 rows), K-tile = 64 keys, D = 64.
// ---------------------------------------------------------------------------
__global__ __launch_bounds__(128) void attn_mma_kernel(
    const float* __restrict__ Q, const float* __restrict__ K,
    const float* __restrict__ V, float* __restrict__ O)
{
    __shared__ uint32_t Ks[64][68];
    __shared__ uint32_t Vs[64][72];

    const int tid  = threadIdx.x;
    const int lane = tid & 31;
    const int warp = tid >> 5;
    const int lq   = lane >> 2;
    const int lr   = lane & 3;
    const int qt = blockIdx.x, h = blockIdx.y, b = blockIdx.z;

    const size_t bho = (size_t)(b * HH + h) * SS * DD;
    const float* Qb = Q + bho;
    const float* Kb = K + bho;
    const float* Vb = V + bho;

    const int q0  = qt * 64 + warp * 16;
    const int qg0 = q0 + lq;        // row A (acc c0,c1)
    const int qg1 = q0 + lq + 8;    // row B (acc c2,c3)

    // Q fragments, pre-scaled by 1/sqrt(64)=0.125, tf32
    uint32_t qa[8][4];
#pragma unroll
    for (int kk8 = 0; kk8 < 8; kk8++) {
        const int d0 = kk8 * 8;
        qa[kk8][0] = f2tf32(Qb[(size_t)qg0 * DD + d0 + lr]     * 0.125f);
        qa[kk8][1] = f2tf32(Qb[(size_t)qg1 * DD + d0 + lr]     * 0.125f);
        qa[kk8][2] = f2tf32(Qb[(size_t)qg0 * DD + d0 + lr + 4] * 0.125f);
        qa[kk8][3] = f2tf32(Qb[(size_t)qg1 * DD + d0 + lr + 4] * 0.125f);
    }

    float oacc[8][4];
#pragma unroll
    for (int nt = 0; nt < 8; nt++)
#pragma unroll
        for (int t = 0; t < 4; t++) oacc[nt][t] = 0.f;
    float m0 = -1e30f, m1 = -1e30f, l0 = 0.f, l1 = 0.f;

    for (int kt = 0; kt <= qt; kt++) {
        __syncthreads();   // prior tile's PV reads of Ks(P)/Vs are done
#pragma unroll
        for (int i = 0; i < 8; i++) {
            const int idx = i * 128 + tid;
            const int row = idx >> 4;
            const int c4  = (idx & 15) << 2;
            float4 kv = *(const float4*)&Kb[(size_t)(kt * 64 + row) * DD + c4];
            float4 vv = *(const float4*)&Vb[(size_t)(kt * 64 + row) * DD + c4];
            Ks[row][c4+0] = f2tf32(kv.x); Ks[row][c4+1] = f2tf32(kv.y);
            Ks[row][c4+2] = f2tf32(kv.z); Ks[row][c4+3] = f2tf32(kv.w);
            Vs[row][c4+0] = f2tf32(vv.x); Vs[row][c4+1] = f2tf32(vv.y);
            Vs[row][c4+2] = f2tf32(vv.z); Vs[row][c4+3] = f2tf32(vv.w);
        }
        __syncthreads();

        // --- scores: S = (Q*scale) . K^T ---
        float sacc[8][4];
#pragma unroll
        for (int nt = 0; nt < 8; nt++)
#pragma unroll
            for (int t = 0; t < 4; t++) sacc[nt][t] = 0.f;
#pragma unroll
        for (int kk8 = 0; kk8 < 8; kk8++) {
#pragma unroll
            for (int nt = 0; nt < 8; nt++) {
                uint32_t bf[2];
                bf[0] = Ks[nt * 8 + lq][kk8 * 8 + lr];
                bf[1] = Ks[nt * 8 + lq][kk8 * 8 + lr + 4];
                mma_tf32(sacc[nt], qa[kk8], bf);
            }
        }

        // --- causal mask + row max ---
        float rmax0 = m0, rmax1 = m1;
#pragma unroll
        for (int nt = 0; nt < 8; nt++) {
            const int gk = kt * 64 + nt * 8 + 2 * lr;
            if (gk     > qg0) sacc[nt][0] = -1e30f;
            if (gk + 1 > qg0) sacc[nt][1] = -1e30f;
            if (gk     > qg1) sacc[nt][2] = -1e30f;
            if (gk + 1 > qg1) sacc[nt][3] = -1e30f;
            rmax0 = fmaxf(rmax0, fmaxf(sacc[nt][0], sacc[nt][1]));
            rmax1 = fmaxf(rmax1, fmaxf(sacc[nt][2], sacc[nt][3]));
        }
        rmax0 = fmaxf(rmax0, __shfl_xor_sync(0xffffffffu, rmax0, 1));
        rmax0 = fmaxf(rmax0, __shfl_xor_sync(0xffffffffu, rmax0, 2));
        rmax1 = fmaxf(rmax1, __shfl_xor_sync(0xffffffffu, rmax1, 1));
        rmax1 = fmaxf(rmax1, __shfl_xor_sync(0xffffffffu, rmax1, 2));

        const float a0 = __expf(m0 - rmax0);
        const float a1 = __expf(m1 - rmax1);
        m0 = rmax0; m1 = rmax1;

        float ls0 = 0.f, ls1 = 0.f;
#pragma unroll
        for (int nt = 0; nt < 8; nt++) {
            sacc[nt][0] = __expf(sacc[nt][0] - m0);
            sacc[nt][1] = __expf(sacc[nt][1] - m0);
            sacc[nt][2] = __expf(sacc[nt][2] - m1);
            sacc[nt][3] = __expf(sacc[nt][3] - m1);
            ls0 += sacc[nt][0] + sacc[nt][1];
            ls1 += sacc[nt][2] + sacc[nt][3];
        }
        ls0 += __shfl_xor_sync(0xffffffffu, ls0, 1);
        ls0 += __shfl_xor_sync(0xffffffffu, ls0, 2);
        ls1 += __shfl_xor_sync(0xffffffffu, ls1, 1);
        ls1 += __shfl_xor_sync(0xffffffffu, ls1, 2);
        l0 = l0 * a0 + ls0;
        l1 = l1 * a1 + ls1;

#pragma unroll
        for (int nt = 0; nt < 8; nt++) {
            oacc[nt][0] *= a0; oacc[nt][1] *= a0;
            oacc[nt][2] *= a1; oacc[nt][3] *= a1;
        }

        __syncthreads();   // all warps done reading Ks -> safe to overwrite with P

        uint32_t* Ps = &Ks[warp * 16][0];
#pragma unroll
        for (int nt = 0; nt < 8; nt++) {
            uint2 p0 = make_uint2(f2tf32(sacc[nt][0]), f2tf32(sacc[nt][1]));
            uint2 p1 = make_uint2(f2tf32(sacc[nt][2]), f2tf32(sacc[nt][3]));
            *(uint2*)&Ps[lq * 68 + nt * 8 + 2 * lr]       = p0;
            *(uint2*)&Ps[(lq + 8) * 68 + nt * 8 + 2 * lr] = p1;
        }
        __syncwarp();

        // --- O += P . V ---
#pragma unroll
        for (int kk8 = 0; kk8 < 8; kk8++) {
            uint32_t af[4];
            af[0] = Ps[lq * 68 + kk8 * 8 + lr];
            af[1] = Ps[(lq + 8) * 68 + kk8 * 8 + lr];
            af[2] = Ps[lq * 68 + kk8 * 8 + lr + 4];
            af[3] = Ps[(lq + 8) * 68 + kk8 * 8 + lr + 4];
#pragma unroll
            for (int nt = 0; nt < 8; nt++) {
                uint32_t bf[2];
                bf[0] = Vs[kk8 * 8 + lr][nt * 8 + lq];
                bf[1] = Vs[kk8 * 8 + lr + 4][nt * 8 + lq];
                mma_tf32(oacc[nt], af, bf);
            }
        }
    }

    // epilogue: normalize, write [B,S,E] row-major for the proj GEMM
    const float inv0 = 1.f / l0;
    const float inv1 = 1.f / l1;
    const size_t r0 = (size_t)(b * SS + qg0) * EE + h * 64;
    const size_t r1 = (size_t)(b * SS + qg1) * EE + h * 64;
#pragma unroll
    for (int nt = 0; nt < 8; nt++) {
        float2 v0 = make_float2(oacc[nt][0] * inv0, oacc[nt][1] * inv0);
        float2 v1 = make_float2(oacc[nt][2] * inv1, oacc[nt][3] * inv1);
        *(float2*)&O[r0 + nt * 8 + 2 * lr] = v0;
        *(float2*)&O[r1 + nt * 8 + 2 * lr] = v1;
    }
}

// ---------------------------------------------------------------------------
extern "C" void kernel_launch(void* const* d_in, const int* in_sizes, int n_in,
                              void* d_out, int out_size)
{
    const float* x      = (const float*)d_in[0];
    const float* qkv_w  = (const float*)d_in[1];
    const float* qkv_b  = (const float*)d_in[2];
    const float* proj_w = (const float*)d_in[3];
    const float* proj_b = (const float*)d_in[4];
    float* out = (float*)d_out;

    float *qbuf, *attnbuf, *kscr, *vscr;
    cudaGetSymbolAddress((void**)&qbuf,    g_q);
    cudaGetSymbolAddress((void**)&attnbuf, g_attn);
    cudaGetSymbolAddress((void**)&kscr,    g_kscr);
    cudaGetSymbolAddress((void**)&vscr,    g_vscr);

    const bool kv_in_out = (out_size >= 3*OUTN);
    float* kdst = kv_in_out ? (out + OUTN)   : kscr;
    float* vdst = kv_in_out ? (out + 2*OUTN) : vscr;

    cudaFuncSetAttribute(mma_gemm_kernel<N3, 1>,
                         cudaFuncAttributeMaxDynamicSharedMemorySize, GEMM_SMEM_BYTES);
    cudaFuncSetAttribute(mma_gemm_kernel<EE, 0>,
                         cudaFuncAttributeMaxDynamicSharedMemorySize, GEMM_SMEM_BYTES);

    mma_gemm_kernel<N3, 1><<<dim3(N3/128, MM/128), 256, GEMM_SMEM_BYTES>>>(
        x, qkv_w, qkv_b, qbuf, kdst, vdst);
    attn_mma_kernel<<<dim3(SS/64, HH, BB), 128>>>(qbuf, kdst, vdst, attnbuf);
    mma_gemm_kernel<EE, 0><<<dim3(EE/128, MM/128), 256, GEMM_SMEM_BYTES>>>(
        attnbuf, proj_w, proj_b, out, nullptr, nullptr);
}